// round 1
// baseline (speedup 1.0000x reference)
#include <cuda_runtime.h>

// ---------------- problem constants ----------------
#define HD    256          // hidden dim
#define BSZ   256          // graphs
#define MAXN  128
#define MAXE  256
#define MAXC  64
#define NLAY  4
#define OUTD  10
#define PN    131072       // node up-pairs
#define PE    98304        // edge up-pairs
#define QE    131072       // edge->node incidences
#define QC    65536        // cell->edge incidences

#define NN (BSZ*MAXN)      // 32768 node rows
#define NE (BSZ*MAXE)      // 65536 edge rows
#define NC (BSZ*MAXC)      // 16384 cell rows

// ---------------- device scratch (no runtime allocation allowed) ----------------
__device__ float g_xn[2][(size_t)NN*HD];
__device__ float g_xe[2][(size_t)NE*HD];
__device__ float g_xc[2][(size_t)NC*HD];
__device__ float g_UN[(size_t)NN*HD];
__device__ float g_VN[(size_t)NE*HD];
__device__ float g_UPN[(size_t)NN*HD];
__device__ float g_UE[(size_t)NE*HD];
__device__ float g_VC[(size_t)NC*HD];
__device__ float g_UPE[(size_t)NE*HD];
__device__ float g_BDFE[(size_t)NE*HD];
__device__ float g_BDE[(size_t)NE*HD];
__device__ float g_BDFC[(size_t)NC*HD];
__device__ float g_BDC[(size_t)NC*HD];
__device__ unsigned g_maske[(size_t)BSZ*MAXE*MAXN/32];
__device__ unsigned g_maskc[(size_t)BSZ*MAXC*MAXE/32];
__device__ unsigned char g_flage[QE];
__device__ unsigned char g_flagc[QC];
__device__ float g_pooled[3][(size_t)BSZ*HD];
__device__ float g_hsum[(size_t)BSZ*2*HD];

// ---------------- tiled SGEMM with fused epilogue ----------------
// C[M,N] = op(A[M,K] @ B[K,N] + bias[N] + add1 + add2); op = relu if relu!=0;
// then += addpost.  M,N multiples of 128; K multiple of 8. All row-major fp32.
__global__ __launch_bounds__(256) void sgemm_ep(
    const float* __restrict__ A, const float* __restrict__ B,
    const float* __restrict__ bias,
    const float* __restrict__ add1, const float* __restrict__ add2,
    const float* __restrict__ addpost,
    float* __restrict__ C, int M, int N, int K, int do_relu)
{
    __shared__ float As[8][128];
    __shared__ float Bs[8][128];

    const int tid = threadIdx.x;
    const int m0  = blockIdx.y * 128;
    const int n0  = blockIdx.x * 128;

    const int a_row = tid >> 1;            // 0..127
    const int a_col = (tid & 1) << 2;      // 0 or 4
    const int b_row = tid >> 5;            // 0..7
    const int b_col = (tid & 31) << 2;     // 0..124
    const int tm    = (tid >> 4) << 3;     // 0..120
    const int tn    = (tid & 15) << 3;     // 0..120

    float acc[8][8];
    #pragma unroll
    for (int i = 0; i < 8; i++)
        #pragma unroll
        for (int j = 0; j < 8; j++) acc[i][j] = 0.f;

    const float* Ap = A + (size_t)(m0 + a_row) * K + a_col;
    const float* Bp = B + (size_t)b_row * N + n0 + b_col;

    for (int k0 = 0; k0 < K; k0 += 8) {
        float4 av = *reinterpret_cast<const float4*>(Ap + k0);
        float4 bv = *reinterpret_cast<const float4*>(Bp + (size_t)k0 * N);
        As[a_col + 0][a_row] = av.x;
        As[a_col + 1][a_row] = av.y;
        As[a_col + 2][a_row] = av.z;
        As[a_col + 3][a_row] = av.w;
        *reinterpret_cast<float4*>(&Bs[b_row][b_col]) = bv;
        __syncthreads();

        #pragma unroll
        for (int kk = 0; kk < 8; kk++) {
            float4 a0 = *reinterpret_cast<const float4*>(&As[kk][tm]);
            float4 a1 = *reinterpret_cast<const float4*>(&As[kk][tm + 4]);
            float4 b0 = *reinterpret_cast<const float4*>(&Bs[kk][tn]);
            float4 b1 = *reinterpret_cast<const float4*>(&Bs[kk][tn + 4]);
            float ar[8] = {a0.x, a0.y, a0.z, a0.w, a1.x, a1.y, a1.z, a1.w};
            float br[8] = {b0.x, b0.y, b0.z, b0.w, b1.x, b1.y, b1.z, b1.w};
            #pragma unroll
            for (int i = 0; i < 8; i++)
                #pragma unroll
                for (int j = 0; j < 8; j++)
                    acc[i][j] = fmaf(ar[i], br[j], acc[i][j]);
        }
        __syncthreads();
    }

    #pragma unroll
    for (int i = 0; i < 8; i++) {
        size_t off = (size_t)(m0 + tm + i) * N + n0 + tn;
        #pragma unroll
        for (int j = 0; j < 8; j += 4) {
            float4 v = make_float4(acc[i][j], acc[i][j+1], acc[i][j+2], acc[i][j+3]);
            int col = n0 + tn + j;
            if (bias) {
                v.x += bias[col];   v.y += bias[col+1];
                v.z += bias[col+2]; v.w += bias[col+3];
            }
            if (add1) {
                float4 a = *reinterpret_cast<const float4*>(add1 + off + j);
                v.x += a.x; v.y += a.y; v.z += a.z; v.w += a.w;
            }
            if (add2) {
                float4 a = *reinterpret_cast<const float4*>(add2 + off + j);
                v.x += a.x; v.y += a.y; v.z += a.z; v.w += a.w;
            }
            if (do_relu) {
                v.x = fmaxf(v.x, 0.f); v.y = fmaxf(v.y, 0.f);
                v.z = fmaxf(v.z, 0.f); v.w = fmaxf(v.w, 0.f);
            }
            if (addpost) {
                float4 a = *reinterpret_cast<const float4*>(addpost + off + j);
                v.x += a.x; v.y += a.y; v.z += a.z; v.w += a.w;
            }
            *reinterpret_cast<float4*>(C + off + j) = v;
        }
    }
}

// ---------------- per-pair up-message: out[i] += relu(U[j] + V[a]) ----------------
__global__ void up_pair_kernel(
    const float* __restrict__ U, const float* __restrict__ V,
    float* __restrict__ out,
    const int* __restrict__ pb, const int* __restrict__ pi,
    const int* __restrict__ pj, const int* __restrict__ pa,
    int P, int mult_ij, int mult_a)
{
    int w = (blockIdx.x * blockDim.x + threadIdx.x) >> 5;
    int lane = threadIdx.x & 31;
    if (w >= P) return;
    int b = pb[w];
    size_t dst = ((size_t)b * mult_ij + pi[w]) * HD;
    size_t src = ((size_t)b * mult_ij + pj[w]) * HD;
    size_t att = ((size_t)b * mult_a  + pa[w]) * HD;
    #pragma unroll
    for (int t = 0; t < 2; t++) {
        int c = (lane << 2) + (t << 7);
        float4 u = *reinterpret_cast<const float4*>(U + src + c);
        float4 v = *reinterpret_cast<const float4*>(V + att + c);
        float4 r;
        r.x = fmaxf(u.x + v.x, 0.f);
        r.y = fmaxf(u.y + v.y, 0.f);
        r.z = fmaxf(u.z + v.z, 0.f);
        r.w = fmaxf(u.w + v.w, 0.f);
        atomicAdd(out + dst + c + 0, r.x);
        atomicAdd(out + dst + c + 1, r.y);
        atomicAdd(out + dst + c + 2, r.z);
        atomicAdd(out + dst + c + 3, r.w);
    }
}

// ---------------- boundary incidence dedup (scatter-SET semantics) ----------------
__global__ void dedup_kernel(
    const int* __restrict__ qb, const int* __restrict__ qi, const int* __restrict__ qj,
    int Q, int di, int dj, unsigned* __restrict__ mask, unsigned char* __restrict__ flag)
{
    int q = blockIdx.x * blockDim.x + threadIdx.x;
    if (q >= Q) return;
    unsigned flat = ((unsigned)qb[q] * di + qi[q]) * dj + qj[q];
    unsigned bit = 1u << (flat & 31u);
    unsigned old = atomicOr(&mask[flat >> 5], bit);
    flag[q] = (old & bit) ? 0 : 1;
}

// ---------------- boundary feature sum: out[i] += X[j] for deduped incidences ----------------
__global__ void bd_scatter_kernel(
    const float* __restrict__ X, float* __restrict__ out,
    const unsigned char* __restrict__ flag,
    const int* __restrict__ qb, const int* __restrict__ qi, const int* __restrict__ qj,
    int Q, int mult_i, int mult_j)
{
    int w = (blockIdx.x * blockDim.x + threadIdx.x) >> 5;
    int lane = threadIdx.x & 31;
    if (w >= Q) return;
    if (!flag[w]) return;
    int b = qb[w];
    size_t dst = ((size_t)b * mult_i + qi[w]) * HD;
    size_t src = ((size_t)b * mult_j + qj[w]) * HD;
    #pragma unroll
    for (int t = 0; t < 2; t++) {
        int c = (lane << 2) + (t << 7);
        float4 v = *reinterpret_cast<const float4*>(X + src + c);
        atomicAdd(out + dst + c + 0, v.x);
        atomicAdd(out + dst + c + 1, v.y);
        atomicAdd(out + dst + c + 2, v.z);
        atomicAdd(out + dst + c + 3, v.w);
    }
}

// ---------------- gated pooling: pooled[b,h] = sum_n sigmoid(G1+G2+bp)*X ----------------
__global__ void pool_kernel(
    const float* __restrict__ X, const float* __restrict__ G1,
    const float* __restrict__ G2, const float* __restrict__ bp,
    float* __restrict__ out, int per)
{
    int b = blockIdx.x;
    int h = threadIdx.x;
    float bias = bp[h];
    float acc = 0.f;
    size_t base = (size_t)b * per * HD + h;
    for (int n = 0; n < per; n++) {
        size_t idx = base + (size_t)n * HD;
        float g = G1[idx] + G2[idx] + bias;
        float w = 1.f / (1.f + expf(-g));
        acc = fmaf(w, X[idx], acc);
    }
    out[(size_t)b * HD + h] = acc;
}

// ---------------- final projection: out[b,o] = hsum[b,:] @ W2 + b2 ----------------
__global__ void final_out_kernel(
    const float* __restrict__ hs, const float* __restrict__ W2,
    const float* __restrict__ b2, float* __restrict__ out)
{
    int b = blockIdx.x;
    int o = threadIdx.x;
    if (o >= OUTD) return;
    float acc = b2[o];
    const float* hr = hs + (size_t)b * 2 * HD;
    for (int k = 0; k < 2 * HD; k++)
        acc = fmaf(hr[k], W2[k * OUTD + o], acc);
    out[b * OUTD + o] = acc;
}

// ---------------- host side ----------------
static float* fsym(const void* symbol) {
    void* p = nullptr;
    cudaGetSymbolAddress(&p, symbol);
    return (float*)p;
}

static void gemm(const float* A, const float* W, const float* bias,
                 const float* add1, const float* add2, const float* addpost,
                 float* C, int M, int N, int K, int relu)
{
    dim3 grid(N / 128, M / 128);
    sgemm_ep<<<grid, 256>>>(A, W, bias, add1, add2, addpost, C, M, N, K, relu);
}

extern "C" void kernel_launch(void* const* d_in, const int* in_sizes, int n_in,
                              void* d_out, int out_size)
{
    (void)in_sizes; (void)n_in; (void)out_size;

    const float* x_n   = (const float*)d_in[0];
    const float* x_e   = (const float*)d_in[1];
    const float* x_c   = (const float*)d_in[2];
    const int* n_up_b  = (const int*)d_in[3];
    const int* n_up_i  = (const int*)d_in[4];
    const int* n_up_j  = (const int*)d_in[5];
    const int* n_up_e  = (const int*)d_in[6];
    const int* e_up_b  = (const int*)d_in[7];
    const int* e_up_i  = (const int*)d_in[8];
    const int* e_up_j  = (const int*)d_in[9];
    const int* e_up_c  = (const int*)d_in[10];
    const int* eb_b    = (const int*)d_in[11];
    const int* eb_i    = (const int*)d_in[12];
    const int* eb_j    = (const int*)d_in[13];
    const int* cb_b    = (const int*)d_in[14];
    const int* cb_i    = (const int*)d_in[15];
    const int* cb_j    = (const int*)d_in[16];
    const float* Wself = (const float*)d_in[17];
    const float* bself = (const float*)d_in[18];
    const float* Wupx  = (const float*)d_in[19];
    const float* Wupa  = (const float*)d_in[20];
    const float* Wb    = (const float*)d_in[21];
    const float* Wp    = (const float*)d_in[22];
    const float* Wp_r  = (const float*)d_in[23];
    const float* bp    = (const float*)d_in[24];
    const float* W1    = (const float*)d_in[25];
    const float* b1    = (const float*)d_in[26];
    const float* W2    = (const float*)d_in[27];
    const float* b2    = (const float*)d_in[28];

    float* xn01 = fsym(g_xn);
    float* xe01 = fsym(g_xe);
    float* xc01 = fsym(g_xc);
    float* bufN[2] = { xn01, xn01 + (size_t)NN * HD };
    float* bufE[2] = { xe01, xe01 + (size_t)NE * HD };
    float* bufC[2] = { xc01, xc01 + (size_t)NC * HD };
    float* UN   = fsym(g_UN);
    float* VN   = fsym(g_VN);
    float* UPN  = fsym(g_UPN);
    float* UE   = fsym(g_UE);
    float* VC   = fsym(g_VC);
    float* UPE  = fsym(g_UPE);
    float* BDFE = fsym(g_BDFE);
    float* BDE  = fsym(g_BDE);
    float* BDFC = fsym(g_BDFC);
    float* BDC  = fsym(g_BDC);
    unsigned* maske = (unsigned*)fsym(g_maske);
    unsigned* maskc = (unsigned*)fsym(g_maskc);
    unsigned char* flage = (unsigned char*)fsym(g_flage);
    unsigned char* flagc = (unsigned char*)fsym(g_flagc);
    float* pooled = fsym(g_pooled);
    float* hsum   = fsym(g_hsum);

    // ---- dedup boundary incidences (fixed across layers) ----
    cudaMemsetAsync(maske, 0, ((size_t)BSZ * MAXE * MAXN / 32) * sizeof(unsigned));
    cudaMemsetAsync(maskc, 0, ((size_t)BSZ * MAXC * MAXE / 32) * sizeof(unsigned));
    dedup_kernel<<<(QE + 255) / 256, 256>>>(eb_b, eb_i, eb_j, QE, MAXE, MAXN, maske, flage);
    dedup_kernel<<<(QC + 255) / 256, 256>>>(cb_b, cb_i, cb_j, QC, MAXC, MAXE, maskc, flagc);

    const float* cxn = x_n;
    const float* cxe = x_e;
    const float* cxc = x_c;

    for (int l = 0; l < NLAY; l++) {
        float* nxn = bufN[l & 1];
        float* nxe = bufE[l & 1];
        float* nxc = bufC[l & 1];

        const float* Wux_n = Wupx + (size_t)(l * 2 + 0) * HD * HD;
        const float* Wux_e = Wupx + (size_t)(l * 2 + 1) * HD * HD;
        const float* Wua_n = Wupa + (size_t)(l * 2 + 0) * HD * HD;
        const float* Wua_e = Wupa + (size_t)(l * 2 + 1) * HD * HD;
        const float* Wb_e  = Wb   + (size_t)(l * 2 + 0) * HD * HD;
        const float* Wb_c  = Wb   + (size_t)(l * 2 + 1) * HD * HD;

        // up messages, node level: up_n[i] += relu((xn Wupx)[j] + (xe Wupa)[a])
        gemm(cxn, Wux_n, 0, 0, 0, 0, UN, NN, HD, HD, 0);
        gemm(cxe, Wua_n, 0, 0, 0, 0, VN, NE, HD, HD, 0);
        cudaMemsetAsync(UPN, 0, (size_t)NN * HD * sizeof(float));
        up_pair_kernel<<<PN / 8, 256>>>(UN, VN, UPN, n_up_b, n_up_i, n_up_j, n_up_e,
                                        PN, MAXN, MAXE);

        // up messages, edge level
        gemm(cxe, Wux_e, 0, 0, 0, 0, UE, NE, HD, HD, 0);
        gemm(cxc, Wua_e, 0, 0, 0, 0, VC, NC, HD, HD, 0);
        cudaMemsetAsync(UPE, 0, (size_t)NE * HD * sizeof(float));
        up_pair_kernel<<<PE / 8, 256>>>(UE, VC, UPE, e_up_b, e_up_i, e_up_j, e_up_c,
                                        PE, MAXE, MAXC);

        // boundary messages (sparse incidence sums, then linear)
        cudaMemsetAsync(BDFE, 0, (size_t)NE * HD * sizeof(float));
        bd_scatter_kernel<<<QE / 8, 256>>>(cxn, BDFE, flage, eb_b, eb_i, eb_j,
                                           QE, MAXE, MAXN);
        gemm(BDFE, Wb_e, 0, 0, 0, 0, BDE, NE, HD, HD, 0);

        cudaMemsetAsync(BDFC, 0, (size_t)NC * HD * sizeof(float));
        bd_scatter_kernel<<<QC / 8, 256>>>(cxe, BDFC, flagc, cb_b, cb_i, cb_j,
                                           QC, MAXC, MAXE);
        gemm(BDFC, Wb_c, 0, 0, 0, 0, BDC, NC, HD, HD, 0);

        // fused self-transform + combine + relu
        gemm(cxn, Wself + (size_t)(l*3+0)*HD*HD, bself + (size_t)(l*3+0)*HD,
             UPN, 0, 0, nxn, NN, HD, HD, 1);
        gemm(cxe, Wself + (size_t)(l*3+1)*HD*HD, bself + (size_t)(l*3+1)*HD,
             UPE, BDE, 0, nxe, NE, HD, HD, 1);
        gemm(cxc, Wself + (size_t)(l*3+2)*HD*HD, bself + (size_t)(l*3+2)*HD,
             BDC, 0, 0, nxc, NC, HD, HD, 1);

        cxn = nxn; cxe = nxe; cxc = nxc;
    }

    // ---- gated pooling per dimension (reuse scratch as gate GEMM outputs) ----
    gemm(cxn, Wp,   0, 0, 0, 0, UN,  NN, HD, HD, 0);
    gemm(x_n, Wp_r, 0, 0, 0, 0, UPN, NN, HD, HD, 0);
    pool_kernel<<<BSZ, HD>>>(cxn, UN, UPN, bp, pooled + 0 * (size_t)BSZ * HD, MAXN);

    gemm(cxe, Wp,   0, 0, 0, 0, UE,  NE, HD, HD, 0);
    gemm(x_e, Wp_r, 0, 0, 0, 0, UPE, NE, HD, HD, 0);
    pool_kernel<<<BSZ, HD>>>(cxe, UE, UPE, bp, pooled + 1 * (size_t)BSZ * HD, MAXE);

    gemm(cxc, Wp,   0, 0, 0, 0, VC,   NC, HD, HD, 0);
    gemm(x_c, Wp_r, 0, 0, 0, 0, BDFC, NC, HD, HD, 0);
    pool_kernel<<<BSZ, HD>>>(cxc, VC, BDFC, bp, pooled + 2 * (size_t)BSZ * HD, MAXC);

    // ---- readout: hsum = sum_i relu(pooled_i @ W1_i + b1_i); out = hsum @ W2 + b2 ----
    gemm(pooled + 0 * (size_t)BSZ * HD, W1 + 0 * (size_t)HD * 2 * HD, b1 + 0 * 2 * HD,
         0, 0, 0,    hsum, BSZ, 2 * HD, HD, 1);
    gemm(pooled + 1 * (size_t)BSZ * HD, W1 + 1 * (size_t)HD * 2 * HD, b1 + 1 * 2 * HD,
         0, 0, hsum, hsum, BSZ, 2 * HD, HD, 1);
    gemm(pooled + 2 * (size_t)BSZ * HD, W1 + 2 * (size_t)HD * 2 * HD, b1 + 2 * 2 * HD,
         0, 0, hsum, hsum, BSZ, 2 * HD, HD, 1);

    final_out_kernel<<<BSZ, 32>>>(hsum, W2, b2, (float*)d_out);
}

// round 3
// speedup vs baseline: 1.5073x; 1.5073x over previous
#include <cuda_runtime.h>
#include <cstdint>

// ---------------- problem constants ----------------
#define HD    256
#define BSZ   256
#define MAXN  128
#define MAXE  256
#define MAXC  64
#define NLAY  4
#define OUTD  10
#define PN    131072
#define PE    98304
#define QE    131072
#define QC    65536

#define NN (BSZ*MAXN)
#define NE (BSZ*MAXE)
#define NC (BSZ*MAXC)

// ---------------- device scratch ----------------
__device__ float g_xn[2][(size_t)NN*HD];
__device__ float g_xe[2][(size_t)NE*HD];
__device__ float g_xc[2][(size_t)NC*HD];
__device__ float g_UN[(size_t)NN*HD];
__device__ float g_VN[(size_t)NE*HD];
__device__ float g_UPN[(size_t)NN*HD];
__device__ float g_UE[(size_t)NE*HD];
__device__ float g_VC[(size_t)NC*HD];
__device__ float g_UPE[(size_t)NE*HD];
__device__ float g_BDFE[(size_t)NE*HD];
__device__ float g_BDE[(size_t)NE*HD];
__device__ float g_BDFC[(size_t)NC*HD];
__device__ float g_BDC[(size_t)NC*HD];
__device__ unsigned g_maske[(size_t)BSZ*MAXE*MAXN/32];
__device__ unsigned g_maskc[(size_t)BSZ*MAXC*MAXE/32];
__device__ unsigned char g_flage[QE];
__device__ unsigned char g_flagc[QC];
__device__ float g_pooled[3][(size_t)BSZ*HD];
__device__ float g_hsum[(size_t)BSZ*2*HD];
__device__ float g_WT[(size_t)38*65536 + (size_t)3*512*256];

// ---------------- PTX helpers (base ISA only, no 'a' features) ----------------
__device__ __forceinline__ uint32_t s2u(const void* p) {
    uint32_t a;
    asm("{ .reg .u64 t; cvta.to.shared.u64 t, %1; cvt.u32.u64 %0, t; }"
        : "=r"(a) : "l"(p));
    return a;
}

__device__ __forceinline__ void cp16(uint32_t sa, const void* g) {
    asm volatile("cp.async.cg.shared.global [%0], [%1], 16;" :: "r"(sa), "l"(g));
}
#define CP_COMMIT() asm volatile("cp.async.commit_group;" ::: "memory")
#define CP_WAIT(n)  asm volatile("cp.async.wait_group %0;" :: "n"(n) : "memory")

__device__ __forceinline__ uint32_t tf32u(float x) {
    uint32_t r;
    asm("cvt.rna.tf32.f32 %0, %1;" : "=r"(r) : "f"(x));
    return r;
}

__device__ __forceinline__ void mma8(float* d, const uint32_t* a, const uint32_t* b) {
    asm volatile(
        "mma.sync.aligned.m16n8k8.row.col.f32.tf32.tf32.f32 "
        "{%0,%1,%2,%3}, {%4,%5,%6,%7}, {%8,%9}, {%0,%1,%2,%3};"
        : "+f"(d[0]), "+f"(d[1]), "+f"(d[2]), "+f"(d[3])
        : "r"(a[0]), "r"(a[1]), "r"(a[2]), "r"(a[3]), "r"(b[0]), "r"(b[1]));
}

__device__ __forceinline__ void red4(float* p, float4 v) {
    asm volatile("red.global.add.v4.f32 [%0], {%1, %2, %3, %4};"
                 :: "l"(p), "f"(v.x), "f"(v.y), "f"(v.z), "f"(v.w) : "memory");
}

// ---------------- 3xTF32 tensor-core GEMM ----------------
// C[M,Ntot] = op(A[M,256] @ BT[Ntot,256]^T + bias + add1 + add2); relu; += addpost
// Block tile 128x128, 8 warps (2m x 4n), warp tile 64x32, K=256 in 8 chunks of 32.
#define KPAD 36                 // padded floats per smem row (conflict-free frags)
#define STAGE_F (128*KPAD*2)    // floats per stage (A tile + B tile)
#define MMAG_SMEM (2*STAGE_F*4) // bytes

__global__ __launch_bounds__(256, 1) void mma_gemm(
    const float* __restrict__ A, const float* __restrict__ BT,
    const float* __restrict__ bias,
    const float* __restrict__ add1, const float* __restrict__ add2,
    const float* __restrict__ addpost,
    float* __restrict__ C, int Ntot, int do_relu)
{
    extern __shared__ __align__(16) float smem[];
    const int tid = threadIdx.x;
    const int wid = tid >> 5, lane = tid & 31;
    const int wm = wid & 1;          // 0..1  (64 rows each)
    const int wn = wid >> 1;         // 0..3  (32 cols each)
    const int g = lane >> 2, t = lane & 3;
    const int m0 = blockIdx.y * 128;
    const int n0 = blockIdx.x * 128;
    const uint32_t sb = s2u(smem);

    const float* Ag = A + (size_t)m0 * 256;
    const float* Bg = BT + (size_t)n0 * 256;

    float acc[4][4][4];
    #pragma unroll
    for (int i = 0; i < 4; i++)
        #pragma unroll
        for (int j = 0; j < 4; j++)
            #pragma unroll
            for (int k = 0; k < 4; k++) acc[i][j][k] = 0.f;

    // ---- async stage loader: A rows 128 x 32 floats + B rows 128 x 32 floats ----
    auto load_stage = [&](int stage, int k0) {
        uint32_t base = sb + (uint32_t)stage * STAGE_F * 4;
        #pragma unroll
        for (int i = 0; i < 4; i++) {
            int idx = i * 256 + tid;           // 0..1023
            int row = idx >> 3, f4 = idx & 7;
            cp16(base + (uint32_t)(row * KPAD + f4 * 4) * 4,
                 Ag + (size_t)row * 256 + k0 + f4 * 4);
        }
        uint32_t bbase = base + 128 * KPAD * 4;
        #pragma unroll
        for (int i = 0; i < 4; i++) {
            int idx = i * 256 + tid;
            int row = idx >> 3, f4 = idx & 7;
            cp16(bbase + (uint32_t)(row * KPAD + f4 * 4) * 4,
                 Bg + (size_t)row * 256 + k0 + f4 * 4);
        }
        CP_COMMIT();
    };

    load_stage(0, 0);

    for (int c = 0; c < 8; c++) {
        if (c < 7) load_stage((c + 1) & 1, (c + 1) * 32);
        if (c < 7) { CP_WAIT(1); } else { CP_WAIT(0); }
        __syncthreads();

        const float* As = smem + (c & 1) * STAGE_F;
        const float* Bs = As + 128 * KPAD;
        const int ar0 = wm * 64;
        const int bc0 = wn * 32;

        #pragma unroll
        for (int ks = 0; ks < 4; ks++) {
            const int kk = ks * 8;
            uint32_t ah[4][4], al[4][4];
            #pragma unroll
            for (int mt = 0; mt < 4; mt++) {
                const float* Ab = As + (ar0 + mt * 16 + g) * KPAD + kk + t;
                float a0 = Ab[0];
                float a1 = Ab[8 * KPAD];
                float a2 = Ab[4];
                float a3 = Ab[8 * KPAD + 4];
                ah[mt][0] = tf32u(a0); al[mt][0] = tf32u(a0 - __uint_as_float(ah[mt][0]));
                ah[mt][1] = tf32u(a1); al[mt][1] = tf32u(a1 - __uint_as_float(ah[mt][1]));
                ah[mt][2] = tf32u(a2); al[mt][2] = tf32u(a2 - __uint_as_float(ah[mt][2]));
                ah[mt][3] = tf32u(a3); al[mt][3] = tf32u(a3 - __uint_as_float(ah[mt][3]));
            }
            uint32_t bh[4][2], bl[4][2];
            #pragma unroll
            for (int nt = 0; nt < 4; nt++) {
                const float* Bb = Bs + (bc0 + nt * 8 + g) * KPAD + kk + t;
                float b0 = Bb[0];
                float b1 = Bb[4];
                bh[nt][0] = tf32u(b0); bl[nt][0] = tf32u(b0 - __uint_as_float(bh[nt][0]));
                bh[nt][1] = tf32u(b1); bl[nt][1] = tf32u(b1 - __uint_as_float(bh[nt][1]));
            }
            #pragma unroll
            for (int mt = 0; mt < 4; mt++)
                #pragma unroll
                for (int nt = 0; nt < 4; nt++) {
                    mma8(acc[mt][nt], ah[mt], bh[nt]);
                    mma8(acc[mt][nt], al[mt], bh[nt]);
                    mma8(acc[mt][nt], ah[mt], bl[nt]);
                }
        }
        __syncthreads();
    }

    // ---- epilogue ----
    #pragma unroll
    for (int mt = 0; mt < 4; mt++) {
        #pragma unroll
        for (int nt = 0; nt < 4; nt++) {
            const int col = n0 + wn * 32 + nt * 8 + 2 * t;
            #pragma unroll
            for (int h = 0; h < 2; h++) {
                const int row = m0 + wm * 64 + mt * 16 + g + h * 8;
                const size_t off = (size_t)row * Ntot + col;
                float v0 = acc[mt][nt][2 * h];
                float v1 = acc[mt][nt][2 * h + 1];
                if (bias)    { v0 += bias[col]; v1 += bias[col + 1]; }
                if (add1)    { float2 a = *reinterpret_cast<const float2*>(add1 + off);
                               v0 += a.x; v1 += a.y; }
                if (add2)    { float2 a = *reinterpret_cast<const float2*>(add2 + off);
                               v0 += a.x; v1 += a.y; }
                if (do_relu) { v0 = fmaxf(v0, 0.f); v1 = fmaxf(v1, 0.f); }
                if (addpost) { float2 a = *reinterpret_cast<const float2*>(addpost + off);
                               v0 += a.x; v1 += a.y; }
                *reinterpret_cast<float2*>(C + off) = make_float2(v0, v1);
            }
        }
    }
}

// ---------------- weight transpose: [K,N] -> [N,K], grid.z = matrix ----------------
__global__ void transpose_k(const float* __restrict__ in, float* __restrict__ out,
                            int K, int N)
{
    __shared__ float tbuf[32][33];
    const float* I = in + (size_t)blockIdx.z * K * N;
    float* O = out + (size_t)blockIdx.z * K * N;
    int k0 = blockIdx.y * 32, n0 = blockIdx.x * 32;
    int x = threadIdx.x, y = threadIdx.y;
    #pragma unroll
    for (int dy = 0; dy < 32; dy += 8)
        tbuf[y + dy][x] = I[(size_t)(k0 + y + dy) * N + n0 + x];
    __syncthreads();
    #pragma unroll
    for (int dy = 0; dy < 32; dy += 8)
        O[(size_t)(n0 + y + dy) * K + k0 + x] = tbuf[x][y + dy];
}

// ---------------- per-pair up-message: out[i] += relu(U[j] + V[a]) ----------------
__global__ void up_pair_kernel(
    const float* __restrict__ U, const float* __restrict__ V,
    float* __restrict__ out,
    const int* __restrict__ pb, const int* __restrict__ pi,
    const int* __restrict__ pj, const int* __restrict__ pa,
    int P, int mult_ij, int mult_a)
{
    int w = (blockIdx.x * blockDim.x + threadIdx.x) >> 5;
    int lane = threadIdx.x & 31;
    if (w >= P) return;
    int b = pb[w];
    size_t dst = ((size_t)b * mult_ij + pi[w]) * HD;
    size_t src = ((size_t)b * mult_ij + pj[w]) * HD;
    size_t att = ((size_t)b * mult_a  + pa[w]) * HD;
    #pragma unroll
    for (int t = 0; t < 2; t++) {
        int c = (lane << 2) + (t << 7);
        float4 u = *reinterpret_cast<const float4*>(U + src + c);
        float4 v = *reinterpret_cast<const float4*>(V + att + c);
        float4 r;
        r.x = fmaxf(u.x + v.x, 0.f);
        r.y = fmaxf(u.y + v.y, 0.f);
        r.z = fmaxf(u.z + v.z, 0.f);
        r.w = fmaxf(u.w + v.w, 0.f);
        red4(out + dst + c, r);
    }
}

// ---------------- boundary incidence dedup (scatter-SET semantics) ----------------
__global__ void dedup_kernel(
    const int* __restrict__ qb, const int* __restrict__ qi, const int* __restrict__ qj,
    int Q, int di, int dj, unsigned* __restrict__ mask, unsigned char* __restrict__ flag)
{
    int q = blockIdx.x * blockDim.x + threadIdx.x;
    if (q >= Q) return;
    unsigned flat = ((unsigned)qb[q] * di + qi[q]) * dj + qj[q];
    unsigned bit = 1u << (flat & 31u);
    unsigned old = atomicOr(&mask[flat >> 5], bit);
    flag[q] = (old & bit) ? 0 : 1;
}

// ---------------- boundary feature sum ----------------
__global__ void bd_scatter_kernel(
    const float* __restrict__ X, float* __restrict__ out,
    const unsigned char* __restrict__ flag,
    const int* __restrict__ qb, const int* __restrict__ qi, const int* __restrict__ qj,
    int Q, int mult_i, int mult_j)
{
    int w = (blockIdx.x * blockDim.x + threadIdx.x) >> 5;
    int lane = threadIdx.x & 31;
    if (w >= Q) return;
    if (!flag[w]) return;
    int b = qb[w];
    size_t dst = ((size_t)b * mult_i + qi[w]) * HD;
    size_t src = ((size_t)b * mult_j + qj[w]) * HD;
    #pragma unroll
    for (int t = 0; t < 2; t++) {
        int c = (lane << 2) + (t << 7);
        float4 v = *reinterpret_cast<const float4*>(X + src + c);
        red4(out + dst + c, v);
    }
}

// ---------------- gated pooling ----------------
__global__ void pool_kernel(
    const float* __restrict__ X, const float* __restrict__ G1,
    const float* __restrict__ G2, const float* __restrict__ bp,
    float* __restrict__ out, int per)
{
    int b = blockIdx.x;
    int h = threadIdx.x;
    float bias = bp[h];
    float acc = 0.f;
    size_t base = (size_t)b * per * HD + h;
    for (int n = 0; n < per; n++) {
        size_t idx = base + (size_t)n * HD;
        float gg = G1[idx] + G2[idx] + bias;
        float w = 1.f / (1.f + expf(-gg));
        acc = fmaf(w, X[idx], acc);
    }
    out[(size_t)b * HD + h] = acc;
}

// ---------------- final projection ----------------
__global__ void final_out_kernel(
    const float* __restrict__ hs, const float* __restrict__ W2,
    const float* __restrict__ b2, float* __restrict__ out)
{
    int b = blockIdx.x;
    int o = threadIdx.x;
    if (o >= OUTD) return;
    float acc = b2[o];
    const float* hr = hs + (size_t)b * 2 * HD;
    for (int k = 0; k < 2 * HD; k++)
        acc = fmaf(hr[k], W2[k * OUTD + o], acc);
    out[b * OUTD + o] = acc;
}

// ---------------- host side ----------------
static float* fsym(const void* symbol) {
    void* p = nullptr;
    cudaGetSymbolAddress(&p, symbol);
    return (float*)p;
}

static void tgemm(const float* A, const float* BT, const float* bias,
                  const float* a1, const float* a2, const float* post,
                  float* C, int M, int Ntot, int relu)
{
    dim3 grid(Ntot / 128, M / 128);
    mma_gemm<<<grid, 256, MMAG_SMEM>>>(A, BT, bias, a1, a2, post, C, Ntot, relu);
}

extern "C" void kernel_launch(void* const* d_in, const int* in_sizes, int n_in,
                              void* d_out, int out_size)
{
    (void)in_sizes; (void)n_in; (void)out_size;

    cudaFuncSetAttribute(mma_gemm, cudaFuncAttributeMaxDynamicSharedMemorySize, MMAG_SMEM);

    const float* x_n   = (const float*)d_in[0];
    const float* x_e   = (const float*)d_in[1];
    const float* x_c   = (const float*)d_in[2];
    const int* n_up_b  = (const int*)d_in[3];
    const int* n_up_i  = (const int*)d_in[4];
    const int* n_up_j  = (const int*)d_in[5];
    const int* n_up_e  = (const int*)d_in[6];
    const int* e_up_b  = (const int*)d_in[7];
    const int* e_up_i  = (const int*)d_in[8];
    const int* e_up_j  = (const int*)d_in[9];
    const int* e_up_c  = (const int*)d_in[10];
    const int* eb_b    = (const int*)d_in[11];
    const int* eb_i    = (const int*)d_in[12];
    const int* eb_j    = (const int*)d_in[13];
    const int* cb_b    = (const int*)d_in[14];
    const int* cb_i    = (const int*)d_in[15];
    const int* cb_j    = (const int*)d_in[16];
    const float* Wself = (const float*)d_in[17];
    const float* bself = (const float*)d_in[18];
    const float* Wupx  = (const float*)d_in[19];
    const float* Wupa  = (const float*)d_in[20];
    const float* Wb    = (const float*)d_in[21];
    const float* Wp    = (const float*)d_in[22];
    const float* Wp_r  = (const float*)d_in[23];
    const float* bp    = (const float*)d_in[24];
    const float* W1    = (const float*)d_in[25];
    const float* b1    = (const float*)d_in[26];
    const float* W2    = (const float*)d_in[27];
    const float* b2    = (const float*)d_in[28];

    float* xn01 = fsym(g_xn);
    float* xe01 = fsym(g_xe);
    float* xc01 = fsym(g_xc);
    float* bufN[2] = { xn01, xn01 + (size_t)NN * HD };
    float* bufE[2] = { xe01, xe01 + (size_t)NE * HD };
    float* bufC[2] = { xc01, xc01 + (size_t)NC * HD };
    float* UN   = fsym(g_UN);
    float* VN   = fsym(g_VN);
    float* UPN  = fsym(g_UPN);
    float* UE   = fsym(g_UE);
    float* VC   = fsym(g_VC);
    float* UPE  = fsym(g_UPE);
    float* BDFE = fsym(g_BDFE);
    float* BDE  = fsym(g_BDE);
    float* BDFC = fsym(g_BDFC);
    float* BDC  = fsym(g_BDC);
    unsigned* maske = (unsigned*)fsym(g_maske);
    unsigned* maskc = (unsigned*)fsym(g_maskc);
    unsigned char* flage = (unsigned char*)fsym(g_flage);
    unsigned char* flagc = (unsigned char*)fsym(g_flagc);
    float* pooled = fsym(g_pooled);
    float* hsum   = fsym(g_hsum);
    float* WT     = fsym(g_WT);

    float* wtSelf = WT;
    float* wtUpx  = WT + (size_t)12 * 65536;
    float* wtUpa  = WT + (size_t)20 * 65536;
    float* wtB    = WT + (size_t)28 * 65536;
    float* wtP    = WT + (size_t)36 * 65536;
    float* wtPr   = WT + (size_t)37 * 65536;
    float* wtW1   = WT + (size_t)38 * 65536;

    // ---- stage transposed weights ([K,N] -> [N,K]) ----
    dim3 tb(32, 8);
    transpose_k<<<dim3(8, 8, 12), tb>>>(Wself, wtSelf, 256, 256);
    transpose_k<<<dim3(8, 8, 8),  tb>>>(Wupx,  wtUpx,  256, 256);
    transpose_k<<<dim3(8, 8, 8),  tb>>>(Wupa,  wtUpa,  256, 256);
    transpose_k<<<dim3(8, 8, 8),  tb>>>(Wb,    wtB,    256, 256);
    transpose_k<<<dim3(8, 8, 1),  tb>>>(Wp,    wtP,    256, 256);
    transpose_k<<<dim3(8, 8, 1),  tb>>>(Wp_r,  wtPr,   256, 256);
    transpose_k<<<dim3(16, 8, 3), tb>>>(W1,    wtW1,   256, 512);

    // ---- dedup boundary incidences ----
    cudaMemsetAsync(maske, 0, ((size_t)BSZ * MAXE * MAXN / 32) * sizeof(unsigned));
    cudaMemsetAsync(maskc, 0, ((size_t)BSZ * MAXC * MAXE / 32) * sizeof(unsigned));
    dedup_kernel<<<(QE + 255) / 256, 256>>>(eb_b, eb_i, eb_j, QE, MAXE, MAXN, maske, flage);
    dedup_kernel<<<(QC + 255) / 256, 256>>>(cb_b, cb_i, cb_j, QC, MAXC, MAXE, maskc, flagc);

    const float* cxn = x_n;
    const float* cxe = x_e;
    const float* cxc = x_c;

    for (int l = 0; l < NLAY; l++) {
        float* nxn = bufN[l & 1];
        float* nxe = bufE[l & 1];
        float* nxc = bufC[l & 1];

        // up messages, node level
        tgemm(cxn, wtUpx + (size_t)(l * 2 + 0) * 65536, 0, 0, 0, 0, UN, NN, 256, 0);
        tgemm(cxe, wtUpa + (size_t)(l * 2 + 0) * 65536, 0, 0, 0, 0, VN, NE, 256, 0);
        cudaMemsetAsync(UPN, 0, (size_t)NN * HD * sizeof(float));
        up_pair_kernel<<<PN / 8, 256>>>(UN, VN, UPN, n_up_b, n_up_i, n_up_j, n_up_e,
                                        PN, MAXN, MAXE);

        // up messages, edge level
        tgemm(cxe, wtUpx + (size_t)(l * 2 + 1) * 65536, 0, 0, 0, 0, UE, NE, 256, 0);
        tgemm(cxc, wtUpa + (size_t)(l * 2 + 1) * 65536, 0, 0, 0, 0, VC, NC, 256, 0);
        cudaMemsetAsync(UPE, 0, (size_t)NE * HD * sizeof(float));
        up_pair_kernel<<<PE / 8, 256>>>(UE, VC, UPE, e_up_b, e_up_i, e_up_j, e_up_c,
                                        PE, MAXE, MAXC);

        // boundary messages (sparse incidence sums, then linear)
        cudaMemsetAsync(BDFE, 0, (size_t)NE * HD * sizeof(float));
        bd_scatter_kernel<<<QE / 8, 256>>>(cxn, BDFE, flage, eb_b, eb_i, eb_j,
                                           QE, MAXE, MAXN);
        tgemm(BDFE, wtB + (size_t)(l * 2 + 0) * 65536, 0, 0, 0, 0, BDE, NE, 256, 0);

        cudaMemsetAsync(BDFC, 0, (size_t)NC * HD * sizeof(float));
        bd_scatter_kernel<<<QC / 8, 256>>>(cxe, BDFC, flagc, cb_b, cb_i, cb_j,
                                           QC, MAXC, MAXE);
        tgemm(BDFC, wtB + (size_t)(l * 2 + 1) * 65536, 0, 0, 0, 0, BDC, NC, 256, 0);

        // fused self-transform + combine + relu
        tgemm(cxn, wtSelf + (size_t)(l * 3 + 0) * 65536, bself + (size_t)(l * 3 + 0) * HD,
              UPN, 0, 0, nxn, NN, 256, 1);
        tgemm(cxe, wtSelf + (size_t)(l * 3 + 1) * 65536, bself + (size_t)(l * 3 + 1) * HD,
              UPE, BDE, 0, nxe, NE, 256, 1);
        tgemm(cxc, wtSelf + (size_t)(l * 3 + 2) * 65536, bself + (size_t)(l * 3 + 2) * HD,
              BDC, 0, 0, nxc, NC, 256, 1);

        cxn = nxn; cxe = nxe; cxc = nxc;
    }

    // ---- gated pooling per dimension ----
    tgemm(cxn, wtP,  0, 0, 0, 0, UN,  NN, 256, 0);
    tgemm(x_n, wtPr, 0, 0, 0, 0, UPN, NN, 256, 0);
    pool_kernel<<<BSZ, HD>>>(cxn, UN, UPN, bp, pooled + 0 * (size_t)BSZ * HD, MAXN);

    tgemm(cxe, wtP,  0, 0, 0, 0, UE,  NE, 256, 0);
    tgemm(x_e, wtPr, 0, 0, 0, 0, UPE, NE, 256, 0);
    pool_kernel<<<BSZ, HD>>>(cxe, UE, UPE, bp, pooled + 1 * (size_t)BSZ * HD, MAXE);

    tgemm(cxc, wtP,  0, 0, 0, 0, VC,   NC, 256, 0);
    tgemm(x_c, wtPr, 0, 0, 0, 0, BDFC, NC, 256, 0);
    pool_kernel<<<BSZ, HD>>>(cxc, VC, BDFC, bp, pooled + 2 * (size_t)BSZ * HD, MAXC);

    // ---- readout ----
    tgemm(pooled + 0 * (size_t)BSZ * HD, wtW1 + 0 * (size_t)512 * 256, b1 + 0 * 512,
          0, 0, 0,    hsum, BSZ, 512, 1);
    tgemm(pooled + 1 * (size_t)BSZ * HD, wtW1 + 1 * (size_t)512 * 256, b1 + 1 * 512,
          0, 0, hsum, hsum, BSZ, 512, 1);
    tgemm(pooled + 2 * (size_t)BSZ * HD, wtW1 + 2 * (size_t)512 * 256, b1 + 2 * 512,
          0, 0, hsum, hsum, BSZ, 512, 1);

    final_out_kernel<<<BSZ, 32>>>(hsum, W2, b2, (float*)d_out);
}